// round 13
// baseline (speedup 1.0000x reference)
#include <cuda_runtime.h>
#include <math.h>

#define Bsz  256
#define Tlen 512
#define Dd   1024
#define Vv   32000
#define EPSV 1e-5f

#define BDIM 256
#define NBLK 128
#define NT   32
#define ASTR 132                    // floats per staged A row (128 + 4 pad)
#define ABUF (64 * ASTR)            // 8448 floats per buffer

#define SM_W_BYTES   (Dd * NT * 4)          // 131072
#define SM_A_BYTES   (2 * ABUF * 4)         // 67584
#define SMEMTOT      (SM_W_BYTES + SM_A_BYTES + 128)

typedef unsigned long long ull;

// ---------------- device scratch ----------------
__device__ float g_u  [Bsz * Dd];
__device__ float g_pre[Bsz * Dd];
__device__ float g_z  [Bsz * Dd];
__device__ unsigned g_flag[NBLK * 32];      // one flag per block, 128B apart

// ---------------- packed fp32x2 ----------------
__device__ __forceinline__ ull ffma2(ull a, ull b, ull c) {
    ull d; asm("fma.rn.f32x2 %0, %1, %2, %3;" : "=l"(d) : "l"(a), "l"(b), "l"(c));
    return d;
}
__device__ __forceinline__ float unpk(ull v) {
    float lo, hi; asm("mov.b64 {%0, %1}, %2;" : "=f"(lo), "=f"(hi) : "l"(v));
    return lo + hi;
}

// ---------------- group barrier: all-to-all release/acquire ----------------
__device__ __forceinline__ unsigned ldacq(const unsigned* p) {
    unsigned v; asm volatile("ld.acquire.gpu.global.u32 %0, [%1];" : "=r"(v) : "l"(p));
    return v;
}
__device__ __forceinline__ void strel(unsigned* p, unsigned v) {
    asm volatile("st.release.gpu.global.u32 [%0], %1;" :: "l"(p), "r"(v) : "memory");
}
__device__ __forceinline__ void gbar(int bid, int g, unsigned ph) {
    __syncthreads();
    if (threadIdx.x == 0) strel(&g_flag[bid * 32], ph);
    if (threadIdx.x < 32) {
        const unsigned* f = &g_flag[(g * 32 + threadIdx.x) * 32];
        while (ldacq(f) < ph) { }
    }
    __syncthreads();
}

// ---------------- block reductions ----------------
__device__ __forceinline__ void blockReduce2(float& s, float& q, float* sm) {
    #pragma unroll
    for (int o = 16; o > 0; o >>= 1) {
        s += __shfl_xor_sync(0xffffffffu, s, o);
        q += __shfl_xor_sync(0xffffffffu, q, o);
    }
    int w = threadIdx.x >> 5;
    if ((threadIdx.x & 31) == 0) { sm[w] = s; sm[8 + w] = q; }
    __syncthreads();
    float ss = 0.f, qq = 0.f;
    #pragma unroll
    for (int i = 0; i < 8; i++) { ss += sm[i]; qq += sm[8 + i]; }
    __syncthreads();
    s = ss; q = qq;
}
__device__ __forceinline__ float blockMax(float v, float* sm) {
    #pragma unroll
    for (int o = 16; o > 0; o >>= 1) v = fmaxf(v, __shfl_xor_sync(0xffffffffu, v, o));
    int w = threadIdx.x >> 5;
    if ((threadIdx.x & 31) == 0) sm[w] = v;
    __syncthreads();
    float r = sm[0];
    #pragma unroll
    for (int i = 1; i < 8; i++) r = fmaxf(r, sm[i]);
    __syncthreads();
    return r;
}
__device__ __forceinline__ float blockSum(float v, float* sm) {
    #pragma unroll
    for (int o = 16; o > 0; o >>= 1) v += __shfl_xor_sync(0xffffffffu, v, o);
    int w = threadIdx.x >> 5;
    if ((threadIdx.x & 31) == 0) sm[w] = v;
    __syncthreads();
    float r = 0.f;
    #pragma unroll
    for (int i = 0; i < 8; i++) r += sm[i];
    __syncthreads();
    return r;
}

// ---- load a 1024x32 B tile into Ws, k-pair interleaved:
//      Ws[(k>>1)*64 + 2n + (k&1)] = Bg[k*ldb + n]
__device__ __forceinline__ void loadB(const float* __restrict__ Bg, int ldb, float* Ws) {
    for (int i = threadIdx.x; i < Dd * NT; i += BDIM) {
        int k = i >> 5, n = i & 31;
        Ws[(k >> 1) * 64 + 2 * n + (k & 1)] = __ldg(Bg + (size_t)k * ldb + n);
    }
}

// ---- GEMM: C[64,32] = A[64,1024] @ B(resident Ws). A staged from global (ld=1024).
// Thread (tx=tid&7, ty=tid>>3): rows 2ty,2ty+1; cols 4tx..4tx+3.
// acc[i][j] packs (even-k, odd-k) partial sums.
__device__ __forceinline__ void gemmRes(const float* __restrict__ Ag,
                                        const float* __restrict__ Ws,
                                        float* As, ull (&acc)[2][4])
{
    const int tid = threadIdx.x, tx = tid & 7, ty = tid >> 3;
    #pragma unroll
    for (int i = 0; i < 2; i++)
        #pragma unroll
        for (int j = 0; j < 4; j++) acc[i][j] = 0ull;

    float4 pf[8];
    #pragma unroll
    for (int q = 0; q < 8; q++) {                       // stage chunk 0
        int f = tid + q * BDIM, m = f >> 5, k4 = f & 31;
        pf[q] = __ldcg((const float4*)(Ag + (size_t)m * Dd + k4 * 4));
    }
    #pragma unroll
    for (int q = 0; q < 8; q++) {
        int f = tid + q * BDIM, m = f >> 5, k4 = f & 31;
        *(float4*)(As + m * ASTR + k4 * 4) = pf[q];
    }
    __syncthreads();

    const float* a0p = As + (2 * ty) * ASTR;
    const float* a1p = As + (2 * ty + 1) * ASTR;
    for (int ch = 0; ch < 8; ch++) {
        const float* Ac0 = a0p + (ch & 1) * ABUF;
        const float* Ac1 = a1p + (ch & 1) * ABUF;
        const float* Wc  = Ws + ch * 4096;              // 64 pairs * 64 floats
        if (ch < 7) {
            int k0 = (ch + 1) * 128;
            #pragma unroll
            for (int q = 0; q < 8; q++) {
                int f = tid + q * BDIM, m = f >> 5, k4 = f & 31;
                pf[q] = __ldcg((const float4*)(Ag + (size_t)m * Dd + k0 + k4 * 4));
            }
        }
        #pragma unroll 16
        for (int p = 0; p < 64; p++) {
            ull a0 = *(const ull*)(Ac0 + 2 * p);
            ull a1 = *(const ull*)(Ac1 + 2 * p);
            ulonglong2 bA = *(const ulonglong2*)(Wc + p * 64 + 8 * tx);
            ulonglong2 bB = *(const ulonglong2*)(Wc + p * 64 + 8 * tx + 4);
            acc[0][0] = ffma2(a0, bA.x, acc[0][0]);
            acc[0][1] = ffma2(a0, bA.y, acc[0][1]);
            acc[0][2] = ffma2(a0, bB.x, acc[0][2]);
            acc[0][3] = ffma2(a0, bB.y, acc[0][3]);
            acc[1][0] = ffma2(a1, bA.x, acc[1][0]);
            acc[1][1] = ffma2(a1, bA.y, acc[1][1]);
            acc[1][2] = ffma2(a1, bB.x, acc[1][2]);
            acc[1][3] = ffma2(a1, bB.y, acc[1][3]);
        }
        if (ch < 7) {
            float* An = As + ((ch + 1) & 1) * ABUF;
            #pragma unroll
            for (int q = 0; q < 8; q++) {
                int f = tid + q * BDIM, m = f >> 5, k4 = f & 31;
                *(float4*)(An + m * ASTR + k4 * 4) = pf[q];
            }
        }
        __syncthreads();
    }
}

// ---------------- persistent kernel ----------------
__global__ void __launch_bounds__(BDIM, 1)
rnn_kernel(const float* __restrict__ hidden,
           const void*  __restrict__ seq,
           const float* __restrict__ emb,
           const float* __restrict__ Wdt,
           const float* __restrict__ bdt,
           const float* __restrict__ gamma,
           const float* __restrict__ beta,
           const float* __restrict__ Wv,
           const float* __restrict__ bv,
           float* __restrict__ outZ,
           float* __restrict__ outY)
{
    extern __shared__ __align__(16) char smem[];
    float* Ws   = (float*)smem;
    float* As   = (float*)(smem + SM_W_BYTES);
    float* sred = (float*)(smem + SM_W_BYTES + SM_A_BYTES);

    const int tid = threadIdx.x, bid = blockIdx.x;
    const int tx = tid & 7, ty = tid >> 3;
    const int g = bid >> 5, l = bid & 31;
    const int mB = g * 64, nB = l * NT;

    unsigned phase = ldacq(&g_flag[bid * 32]);      // monotone across replays

    // ---- index dtype sniff (window safe under either dtype) ----
    int bad = 0;
    {
        const int* s32 = (const int*)seq;
        int base = bid * 1024;
        for (int i = tid; i < 1024; i += BDIM)
            if (((base + i) & 1) && __ldg(s32 + base + i) != 0) bad = 1;
    }
    bad = __syncthreads_or(bad);
    const int is64 = bad ? 0 : 1;

    // ---- c = hidden @ W2 + b_dt, register-resident ----
    float cc[2][4];
    {
        loadB(Wdt + (size_t)Dd * Dd + nB, Dd, Ws);
        __syncthreads();
        ull acc[2][4];
        gemmRes(hidden + (size_t)mB * Dd, Ws, As, acc);
        #pragma unroll
        for (int i = 0; i < 2; i++)
            #pragma unroll
            for (int j = 0; j < 4; j++)
                cc[i][j] = unpk(acc[i][j]) + __ldg(&bdt[nB + 4 * tx + j]);
        __syncthreads();
    }
    // ---- W1 tile resident for all 512 steps ----
    loadB(Wdt + nB, Dd, Ws);

    // ---- u_0 = emb[seq[:,0]]; block owns rows 2*bid, 2*bid+1 ----
    #pragma unroll
    for (int rr = 0; rr < 2; rr++) {
        int row = (bid << 1) + rr;
        int idx = is64 ? (int)__ldg(((const long long*)seq) + (size_t)row * Tlen)
                       :       __ldg(((const int*)seq)       + (size_t)row * Tlen);
        float4 e4 = __ldg(((const float4*)(emb + (size_t)idx * Dd)) + tid);
        __stcg(((float4*)(g_u + (size_t)row * Dd)) + tid, e4);
    }
    phase++; gbar(bid, g, phase);

    const float4 ga4 = __ldg(((const float4*)gamma) + tid);
    const float4 be4 = __ldg(((const float4*)beta)  + tid);

    // ---- recurrence: 512 x (GEMM | LN) ----
    for (int t = 0; t < Tlen; t++) {
        {
            ull acc[2][4];
            gemmRes(g_u + (size_t)mB * Dd, Ws, As, acc);
            #pragma unroll
            for (int i = 0; i < 2; i++) {
                int m = mB + 2 * ty + i;
                size_t off = (size_t)m * Dd + nB + 4 * tx;
                float4 uu = __ldcg((const float4*)(g_u + off));
                float4 po;
                po.x = unpk(acc[i][0]) + cc[i][0] + uu.x;
                po.y = unpk(acc[i][1]) + cc[i][1] + uu.y;
                po.z = unpk(acc[i][2]) + cc[i][2] + uu.z;
                po.w = unpk(acc[i][3]) + cc[i][3] + uu.w;
                __stcg((float4*)(g_pre + off), po);
            }
        }
        phase++; gbar(bid, g, phase);

        #pragma unroll
        for (int rr = 0; rr < 2; rr++) {
            int row = (bid << 1) + rr;
            float4 v = __ldcg(((const float4*)(g_pre + (size_t)row * Dd)) + tid);
            float s = (v.x + v.y) + (v.z + v.w);
            float q = fmaf(v.x, v.x, fmaf(v.y, v.y, fmaf(v.z, v.z, v.w * v.w)));
            blockReduce2(s, q, sred);
            float mean = s * (1.f / Dd);
            float var  = q * (1.f / Dd) - mean * mean;
            float rstd = rsqrtf(var + EPSV);
            float4 z4;
            z4.x = fmaf((v.x - mean) * rstd, ga4.x, be4.x);
            z4.y = fmaf((v.y - mean) * rstd, ga4.y, be4.y);
            z4.z = fmaf((v.z - mean) * rstd, ga4.z, be4.z);
            z4.w = fmaf((v.w - mean) * rstd, ga4.w, be4.w);
            if (t + 1 < Tlen) {
                int idx = is64 ? (int)__ldg(((const long long*)seq) + (size_t)row * Tlen + t + 1)
                               :       __ldg(((const int*)seq)       + (size_t)row * Tlen + t + 1);
                float4 e4 = __ldg(((const float4*)(emb + (size_t)idx * Dd)) + tid);
                float4 u4 = make_float4(z4.x + e4.x, z4.y + e4.y, z4.z + e4.z, z4.w + e4.w);
                __stcg(((float4*)(g_u + (size_t)row * Dd)) + tid, u4);
            } else {
                __stcg(((float4*)(g_z + (size_t)row * Dd)) + tid, z4);
                if (outZ) __stcg(((float4*)(outZ + (size_t)row * Dd)) + tid, z4);
            }
        }
        phase++; gbar(bid, g, phase);
    }

    // ---- logits = z @ W_v + b_v : 1000 col-tiles striped over the 32 blocks ----
    {
        const int nColTiles = Vv / NT;   // 1000
        for (int tc = l; tc < nColTiles; tc += 32) {
            int nB2 = tc * NT;
            loadB(Wv + nB2, Vv, Ws);
            __syncthreads();
            ull acc[2][4];
            gemmRes(g_z + (size_t)mB * Dd, Ws, As, acc);
            #pragma unroll
            for (int i = 0; i < 2; i++) {
                int m = mB + 2 * ty + i;
                size_t off = (size_t)m * Vv + nB2 + 4 * tx;
                float4 oo;
                oo.x = unpk(acc[i][0]) + __ldg(&bv[nB2 + 4 * tx + 0]);
                oo.y = unpk(acc[i][1]) + __ldg(&bv[nB2 + 4 * tx + 1]);
                oo.z = unpk(acc[i][2]) + __ldg(&bv[nB2 + 4 * tx + 2]);
                oo.w = unpk(acc[i][3]) + __ldg(&bv[nB2 + 4 * tx + 3]);
                __stcg((float4*)(outY + off), oo);
            }
            __syncthreads();
        }
    }
    phase++; gbar(bid, g, phase);

    // ---- log_softmax in place on outY rows 2*bid, 2*bid+1 ----
    for (int rr = 0; rr < 2; rr++) {
        int row = (bid << 1) + rr;
        float* lrow = outY + (size_t)row * Vv;
        float m = -3.402823e38f;
        for (int i = tid; i < Vv; i += BDIM) m = fmaxf(m, __ldcg(lrow + i));
        m = blockMax(m, sred);
        float s = 0.f;
        for (int i = tid; i < Vv; i += BDIM) s += expf(__ldcg(lrow + i) - m);
        s = blockSum(s, sred);
        float ls = m + logf(s);
        for (int i = tid; i < Vv; i += BDIM) {
            float v = __ldcg(lrow + i);
            __stcg(lrow + i, v - ls);
        }
    }
}

// ---------------- launch ----------------
extern "C" void kernel_launch(void* const* d_in, const int* in_sizes, int n_in,
                              void* d_out, int out_size) {
    const float* hidden = (const float*)d_in[0];
    const void*  seq    = d_in[1];
    const float* emb    = (const float*)d_in[2];
    const float* Wdt    = (const float*)d_in[3];
    const float* bdt    = (const float*)d_in[4];
    const float* gamma  = (const float*)d_in[5];
    const float* beta   = (const float*)d_in[6];
    const float* Wv     = (const float*)d_in[7];
    const float* bv     = (const float*)d_in[8];
    float* out = (float*)d_out;

    float* outZ;
    float* outY;
    if (out_size >= Bsz * Dd + Bsz * Vv) { outZ = out; outY = out + Bsz * Dd; }
    else                                 { outZ = nullptr; outY = out; }

    cudaFuncSetAttribute(rnn_kernel, cudaFuncAttributeMaxDynamicSharedMemorySize, SMEMTOT);
    rnn_kernel<<<NBLK, BDIM, SMEMTOT>>>(hidden, seq, emb, Wdt, bdt, gamma, beta,
                                        Wv, bv, outZ, outY);
}